// round 1
// baseline (speedup 1.0000x reference)
#include <cuda_runtime.h>
#include <math.h>

// Problem constants: B=16, X=4, I=8 -> G=512 groups; Lc=256, Lq=128, H=512
#define NG 512
#define LCC 256
#define LQQ 128
#define HD 512
#define FSCALE 100.0f
#define FPEN 1.0e12f   // NEG_BIG * SCALE

// Scratch (static device globals: allocation-free per harness rules)
__device__ float g_S [NG * LCC * LQQ];   // masked, scaled logits (64 MB)
__device__ float g_Pc[NG * LCC * LQQ];   // row-softmax probs * mask
__device__ float g_Pq[NG * LCC * LQQ];   // col-softmax probs * mask
__device__ float g_invC[NG * LCC];
__device__ float g_invQ[NG * LQQ];

// ---------------------------------------------------------------------------
// Row L2 inverse norms. One warp per row of H=512 floats.
// sel=0 -> g_invC, sel=1 -> g_invQ
// ---------------------------------------------------------------------------
__global__ void norm_kernel(const float* __restrict__ X, int nrows, int sel) {
    int gw   = (blockIdx.x * blockDim.x + threadIdx.x) >> 5;
    int lane = threadIdx.x & 31;
    if (gw >= nrows) return;
    const float4* row = (const float4*)(X + (size_t)gw * HD);
    float s = 0.f;
#pragma unroll
    for (int i = 0; i < HD / 128; i++) {
        float4 v = row[lane + 32 * i];
        s = fmaf(v.x, v.x, fmaf(v.y, v.y, fmaf(v.z, v.z, fmaf(v.w, v.w, s))));
    }
#pragma unroll
    for (int o = 16; o; o >>= 1) s += __shfl_xor_sync(0xffffffffu, s, o);
    if (lane == 0) {
        float inv = 1.f / fmaxf(sqrtf(s), 1e-12f);
        if (sel) g_invQ[gw] = inv; else g_invC[gw] = inv;
    }
}

// Shared 8x8-per-thread FFMA microkernel over a BK=16 slab.
#define GEMM_MMA()                                                       \
    _Pragma("unroll")                                                    \
    for (int kk = 0; kk < 16; kk++) {                                    \
        float a[8], b[8];                                                \
        _Pragma("unroll") for (int i = 0; i < 8; i++) a[i] = As[kk][ty8 + i]; \
        _Pragma("unroll") for (int j = 0; j < 8; j++) b[j] = Bs[kk][tx8 + j]; \
        _Pragma("unroll") for (int i = 0; i < 8; i++)                    \
            _Pragma("unroll") for (int j = 0; j < 8; j++)                \
                acc[i][j] = fmaf(a[i], b[j], acc[i][j]);                 \
    }

// ---------------------------------------------------------------------------
// S = (C @ Q^T) * invC * invQ, scaled + mask-penalized.
// A = C[g] [256,512] row-major, B[k][n] = Q[g][n][k] (both K-major).
// Tile: BM=128, BN=128 (=Lq), BK=16. grid (1, 2, G), 256 threads.
// ---------------------------------------------------------------------------
__global__ __launch_bounds__(256) void sgemm_S(
    const float* __restrict__ Cin, const float* __restrict__ Qin,
    const float* __restrict__ cm, const float* __restrict__ qm) {
    __shared__ float As[16][132];
    __shared__ float Bs[16][132];
    int g  = blockIdx.z;
    int m0 = blockIdx.y * 128;
    const float* A = Cin + (size_t)g * LCC * HD;
    const float* B = Qin + (size_t)g * LQQ * HD;
    int t = threadIdx.x;
    int tx8 = (t & 15) * 8, ty8 = (t >> 4) * 8;
    float acc[8][8] = {};
    for (int k0 = 0; k0 < HD; k0 += 16) {
#pragma unroll
        for (int i = 0; i < 2; i++) {
            int f  = t + i * 256;
            int r  = f >> 2;
            int c4 = (f & 3) << 2;
            float4 v = *(const float4*)(A + (size_t)(m0 + r) * HD + (k0 + c4));
            As[c4][r] = v.x; As[c4 + 1][r] = v.y; As[c4 + 2][r] = v.z; As[c4 + 3][r] = v.w;
            float4 w = *(const float4*)(B + (size_t)r * HD + (k0 + c4));
            Bs[c4][r] = w.x; Bs[c4 + 1][r] = w.y; Bs[c4 + 2][r] = w.z; Bs[c4 + 3][r] = w.w;
        }
        __syncthreads();
        GEMM_MMA();
        __syncthreads();
    }
    float iq[8], qmv[8];
#pragma unroll
    for (int j = 0; j < 8; j++) {
        iq[j]  = g_invQ[g * LQQ + tx8 + j];
        qmv[j] = qm[g * LQQ + tx8 + j];
    }
    int mbase = m0 + ty8;
#pragma unroll
    for (int i = 0; i < 8; i++) {
        float ic  = g_invC[g * LCC + mbase + i];
        float cmv = cm[g * LCC + mbase + i];
        float* dst = g_S + ((size_t)g * LCC + mbase + i) * LQQ + tx8;
#pragma unroll
        for (int j = 0; j < 8; j += 4) {
            float4 o;
            o.x = FSCALE * acc[i][j    ] * ic * iq[j    ] - FPEN * (1.f - cmv * qmv[j    ]);
            o.y = FSCALE * acc[i][j + 1] * ic * iq[j + 1] - FPEN * (1.f - cmv * qmv[j + 1]);
            o.z = FSCALE * acc[i][j + 2] * ic * iq[j + 2] - FPEN * (1.f - cmv * qmv[j + 2]);
            o.w = FSCALE * acc[i][j + 3] * ic * iq[j + 3] - FPEN * (1.f - cmv * qmv[j + 3]);
            *(float4*)(dst + j) = o;
        }
    }
}

// ---------------------------------------------------------------------------
// Row softmax (over Lq=128) -> P_c = softmax * c_mask * q_mask. Warp per row.
// ---------------------------------------------------------------------------
__global__ void row_softmax(const float* __restrict__ cm, const float* __restrict__ qm) {
    int row = (blockIdx.x * blockDim.x + threadIdx.x) >> 5;
    if (row >= NG * LCC) return;
    int lane = threadIdx.x & 31;
    int g = row >> 8;
    float4 v = ((const float4*)(g_S + (size_t)row * LQQ))[lane];
    float m = fmaxf(fmaxf(v.x, v.y), fmaxf(v.z, v.w));
#pragma unroll
    for (int o = 16; o; o >>= 1) m = fmaxf(m, __shfl_xor_sync(0xffffffffu, m, o));
    float e0 = __expf(v.x - m), e1 = __expf(v.y - m), e2 = __expf(v.z - m), e3 = __expf(v.w - m);
    float sum = (e0 + e1) + (e2 + e3);
#pragma unroll
    for (int o = 16; o; o >>= 1) sum += __shfl_xor_sync(0xffffffffu, sum, o);
    float inv = cm[row] / sum;   // fold c_mask into the normalizer
    float4 qv = ((const float4*)(qm + (size_t)g * LQQ))[lane];
    float4 o4;
    o4.x = e0 * inv * qv.x; o4.y = e1 * inv * qv.y;
    o4.z = e2 * inv * qv.z; o4.w = e3 * inv * qv.w;
    ((float4*)(g_Pc + (size_t)row * LQQ))[lane] = o4;
}

// ---------------------------------------------------------------------------
// Column softmax (over Lc=256) -> P_q = softmax * masks. One block per group,
// 128 threads = one thread per q column; coalesced across threads.
// ---------------------------------------------------------------------------
__global__ void col_softmax(const float* __restrict__ cm, const float* __restrict__ qm) {
    __shared__ float cms[LCC];
    int g = blockIdx.x;
    int q = threadIdx.x;
    for (int c = q; c < LCC; c += 128) cms[c] = cm[g * LCC + c];
    __syncthreads();
    const float* s = g_S + (size_t)g * LCC * LQQ + q;
    float m0 = -3e38f, m1 = -3e38f, m2 = -3e38f, m3 = -3e38f;
#pragma unroll 4
    for (int c = 0; c < LCC; c += 4) {
        m0 = fmaxf(m0, s[(c    ) * LQQ]);
        m1 = fmaxf(m1, s[(c + 1) * LQQ]);
        m2 = fmaxf(m2, s[(c + 2) * LQQ]);
        m3 = fmaxf(m3, s[(c + 3) * LQQ]);
    }
    float m = fmaxf(fmaxf(m0, m1), fmaxf(m2, m3));
    float s0 = 0.f, s1 = 0.f, s2 = 0.f, s3 = 0.f;
#pragma unroll 4
    for (int c = 0; c < LCC; c += 4) {
        s0 += __expf(s[(c    ) * LQQ] - m);
        s1 += __expf(s[(c + 1) * LQQ] - m);
        s2 += __expf(s[(c + 2) * LQQ] - m);
        s3 += __expf(s[(c + 3) * LQQ] - m);
    }
    float inv = qm[g * LQQ + q] / ((s0 + s1) + (s2 + s3));  // fold q_mask
    float* p = g_Pq + (size_t)g * LCC * LQQ + q;
#pragma unroll 4
    for (int c = 0; c < LCC; c++)
        p[c * LQQ] = __expf(s[c * LQQ] - m) * inv * cms[c];
}

// ---------------------------------------------------------------------------
// Mask outputs: S_mask [g,c,q] and S_mask^T [g,q,c].
// ---------------------------------------------------------------------------
__global__ void mask_kernel(const float* __restrict__ cm, const float* __restrict__ qm,
                            float* __restrict__ outM, float* __restrict__ outMT) {
    int i = blockIdx.x * blockDim.x + threadIdx.x;
    int g = i >> 15;
    {
        int q = i & 127, c = (i >> 7) & 255;
        outM[i] = cm[g * LCC + c] * qm[g * LQQ + q];
    }
    {
        int c = i & 255, q = (i >> 8) & 127;
        outMT[i] = cm[g * LCC + c] * qm[g * LQQ + q];
    }
}

// ---------------------------------------------------------------------------
// A_c = P_c @ Q : [256,128] x [128,512] per group. grid (4, 2, G).
// ---------------------------------------------------------------------------
__global__ __launch_bounds__(256) void gemm_Ac(const float* __restrict__ Qin,
                                               float* __restrict__ out) {
    __shared__ float As[16][132];
    __shared__ float Bs[16][132];
    int g  = blockIdx.z;
    int m0 = blockIdx.y * 128;
    int n0 = blockIdx.x * 128;
    const float* A = g_Pc + (size_t)g * LCC * LQQ;  // [256,128] row-major
    const float* B = Qin  + (size_t)g * LQQ * HD;   // [128,512] row-major
    int t = threadIdx.x;
    int tx8 = (t & 15) * 8, ty8 = (t >> 4) * 8;
    float acc[8][8] = {};
    for (int k0 = 0; k0 < LQQ; k0 += 16) {
#pragma unroll
        for (int i = 0; i < 2; i++) {
            int f = t + i * 256;
            int r = f >> 2; int c4 = (f & 3) << 2;
            float4 v = *(const float4*)(A + (size_t)(m0 + r) * LQQ + (k0 + c4));
            As[c4][r] = v.x; As[c4 + 1][r] = v.y; As[c4 + 2][r] = v.z; As[c4 + 3][r] = v.w;
            int kr = f >> 5; int cc = (f & 31) << 2;
            float4 w = *(const float4*)(B + (size_t)(k0 + kr) * HD + (n0 + cc));
            *(float4*)&Bs[kr][cc] = w;
        }
        __syncthreads();
        GEMM_MMA();
        __syncthreads();
    }
#pragma unroll
    for (int i = 0; i < 8; i++) {
        float* dst = out + ((size_t)g * LCC + m0 + ty8 + i) * HD + n0 + tx8;
#pragma unroll
        for (int j = 0; j < 8; j += 4) {
            float4 o = {acc[i][j], acc[i][j + 1], acc[i][j + 2], acc[i][j + 3]};
            *(float4*)(dst + j) = o;
        }
    }
}

// ---------------------------------------------------------------------------
// A_q = P_q^T @ C : [128,256] x [256,512] per group. A stored [K=256][M=128].
// grid (4, 1, G).
// ---------------------------------------------------------------------------
__global__ __launch_bounds__(256) void gemm_Aq(const float* __restrict__ Cin,
                                               float* __restrict__ out) {
    __shared__ float As[16][132];
    __shared__ float Bs[16][132];
    int g  = blockIdx.z;
    int n0 = blockIdx.x * 128;
    const float* A = g_Pq + (size_t)g * LCC * LQQ;  // [256][128]: A[m,k]=A[k*128+m]
    const float* B = Cin  + (size_t)g * LCC * HD;   // [256,512]
    int t = threadIdx.x;
    int tx8 = (t & 15) * 8, ty8 = (t >> 4) * 8;
    float acc[8][8] = {};
    for (int k0 = 0; k0 < LCC; k0 += 16) {
#pragma unroll
        for (int i = 0; i < 2; i++) {
            int f = t + i * 256;
            int kr = f >> 5; int cc = (f & 31) << 2;
            float4 v = *(const float4*)(A + (size_t)(k0 + kr) * LQQ + cc);
            *(float4*)&As[kr][cc] = v;
            float4 w = *(const float4*)(B + (size_t)(k0 + kr) * HD + (n0 + cc));
            *(float4*)&Bs[kr][cc] = w;
        }
        __syncthreads();
        GEMM_MMA();
        __syncthreads();
    }
#pragma unroll
    for (int i = 0; i < 8; i++) {
        float* dst = out + ((size_t)g * LQQ + ty8 + i) * HD + n0 + tx8;
#pragma unroll
        for (int j = 0; j < 8; j += 4) {
            float4 o = {acc[i][j], acc[i][j + 1], acc[i][j + 2], acc[i][j + 3]};
            *(float4*)(dst + j) = o;
        }
    }
}

// ---------------------------------------------------------------------------
extern "C" void kernel_launch(void* const* d_in, const int* in_sizes, int n_in,
                              void* d_out, int out_size) {
    const float* Cin = (const float*)d_in[0];
    const float* Qin = (const float*)d_in[1];
    const float* cm  = (const float*)d_in[2];
    const float* qm  = (const float*)d_in[3];
    float* out   = (float*)d_out;
    float* outAc = out;                                    // [G,256,512]
    float* outAq = outAc + (size_t)NG * LCC * HD;          // [G,128,512]
    float* outM  = outAq + (size_t)NG * LQQ * HD;          // [G,256,128]
    float* outMT = outM  + (size_t)NG * LCC * LQQ;         // [G,128,256]

    norm_kernel<<<NG * LCC / 8, 256>>>(Cin, NG * LCC, 0);
    norm_kernel<<<NG * LQQ / 8, 256>>>(Qin, NG * LQQ, 1);
    sgemm_S<<<dim3(1, 2, NG), 256>>>(Cin, Qin, cm, qm);
    row_softmax<<<NG * LCC / 8, 256>>>(cm, qm);
    col_softmax<<<NG, 128>>>(cm, qm);
    mask_kernel<<<NG * LCC * LQQ / 256, 256>>>(cm, qm, outM, outMT);
    gemm_Ac<<<dim3(4, 2, NG), 256>>>(Qin, outAc);
    gemm_Aq<<<dim3(4, 1, NG), 256>>>(Cin, outAq);
}

// round 3
// speedup vs baseline: 1.0073x; 1.0073x over previous
#include <cuda_runtime.h>
#include <math.h>

// Problem constants: B=16, X=4, I=8 -> G=512 groups; Lc=256, Lq=128, H=512
#define NG 512
#define LCC 256
#define LQQ 128
#define HD 512
#define FSCALE 100.0f
#define FPEN 1.0e12f   // NEG_BIG * SCALE

// Scratch (static device globals: allocation-free per harness rules)
__device__ float g_S [NG * LCC * LQQ];   // masked, scaled logits
__device__ float g_Pc[NG * LCC * LQQ];   // row-softmax probs * mask
__device__ float g_Pq[NG * LCC * LQQ];   // col-softmax probs * mask
__device__ float g_invC[NG * LCC];
__device__ float g_invQ[NG * LQQ];

// ---------------------------------------------------------------------------
// Packed f32x2 helpers (Blackwell sm_100+ baseline PTX; 2 fp32 FMA per slot)
// ---------------------------------------------------------------------------
static __device__ __forceinline__ unsigned long long pack2(float x) {
    unsigned long long r;
    asm("mov.b64 %0, {%1, %1};" : "=l"(r) : "f"(x));
    return r;
}
static __device__ __forceinline__ void fma2(unsigned long long& d,
                                            unsigned long long a,
                                            unsigned long long b) {
    asm("fma.rn.f32x2 %0, %1, %2, %0;" : "+l"(d) : "l"(a), "l"(b));
}
static __device__ __forceinline__ float2 unpack2(unsigned long long v) {
    float lo, hi;
    asm("mov.b64 {%0, %1}, %2;" : "=f"(lo), "=f"(hi) : "l"(v));
    return make_float2(lo, hi);
}

// ---------------------------------------------------------------------------
// Row L2 inverse norms. One warp per row of H=512 floats.
// ---------------------------------------------------------------------------
__global__ void norm_kernel(const float* __restrict__ X, int nrows, int sel) {
    int gw   = (blockIdx.x * blockDim.x + threadIdx.x) >> 5;
    int lane = threadIdx.x & 31;
    if (gw >= nrows) return;
    const float4* row = (const float4*)(X + (size_t)gw * HD);
    float s = 0.f;
#pragma unroll
    for (int i = 0; i < HD / 128; i++) {
        float4 v = row[lane + 32 * i];
        s = fmaf(v.x, v.x, fmaf(v.y, v.y, fmaf(v.z, v.z, fmaf(v.w, v.w, s))));
    }
#pragma unroll
    for (int o = 16; o; o >>= 1) s += __shfl_xor_sync(0xffffffffu, s, o);
    if (lane == 0) {
        float inv = 1.f / fmaxf(sqrtf(s), 1e-12f);
        if (sel) g_invQ[gw] = inv; else g_invC[gw] = inv;
    }
}

// ---------------------------------------------------------------------------
// f32x2 8x8-per-thread microkernel over a BK=16 slab.
// acc2[i][j] holds columns (tx8+2j, tx8+2j+1) of row ty8+i.
// ---------------------------------------------------------------------------
#define GEMM_MMA2()                                                           \
    _Pragma("unroll")                                                         \
    for (int kk = 0; kk < 16; kk++) {                                         \
        float4 av0 = *(const float4*)&As[kk][ty8];                            \
        float4 av1 = *(const float4*)&As[kk][ty8 + 4];                        \
        unsigned long long a2[8];                                             \
        a2[0] = pack2(av0.x); a2[1] = pack2(av0.y);                           \
        a2[2] = pack2(av0.z); a2[3] = pack2(av0.w);                           \
        a2[4] = pack2(av1.x); a2[5] = pack2(av1.y);                           \
        a2[6] = pack2(av1.z); a2[7] = pack2(av1.w);                           \
        const unsigned long long* bp = (const unsigned long long*)&Bs[kk][tx8]; \
        unsigned long long b2[4];                                             \
        b2[0] = bp[0]; b2[1] = bp[1]; b2[2] = bp[2]; b2[3] = bp[3];           \
        _Pragma("unroll") for (int i = 0; i < 8; i++)                         \
            _Pragma("unroll") for (int j = 0; j < 4; j++)                     \
                fma2(acc2[i][j], a2[i], b2[j]);                               \
    }

// ---------------------------------------------------------------------------
// S = (C @ Q^T) * invC * invQ, scaled + mask-penalized.
// Tile: BM=128, BN=128 (=Lq), BK=16. grid (1, 2, G), 256 threads.
// ---------------------------------------------------------------------------
__global__ __launch_bounds__(256) void sgemm_S(
    const float* __restrict__ Cin, const float* __restrict__ Qin,
    const float* __restrict__ cm, const float* __restrict__ qm) {
    __shared__ float As[16][132];
    __shared__ float Bs[16][132];
    int g  = blockIdx.z;
    int m0 = blockIdx.y * 128;
    const float* A = Cin + (size_t)g * LCC * HD;
    const float* B = Qin + (size_t)g * LQQ * HD;
    int t = threadIdx.x;
    int tx8 = (t & 15) * 8, ty8 = (t >> 4) * 8;
    unsigned long long acc2[8][4] = {};
    for (int k0 = 0; k0 < HD; k0 += 16) {
#pragma unroll
        for (int i = 0; i < 2; i++) {
            int f  = t + i * 256;
            int r  = f >> 2;
            int c4 = (f & 3) << 2;
            float4 v = *(const float4*)(A + (size_t)(m0 + r) * HD + (k0 + c4));
            As[c4][r] = v.x; As[c4 + 1][r] = v.y; As[c4 + 2][r] = v.z; As[c4 + 3][r] = v.w;
            float4 w = *(const float4*)(B + (size_t)r * HD + (k0 + c4));
            Bs[c4][r] = w.x; Bs[c4 + 1][r] = w.y; Bs[c4 + 2][r] = w.z; Bs[c4 + 3][r] = w.w;
        }
        __syncthreads();
        GEMM_MMA2();
        __syncthreads();
    }
    float iq[8], qmv[8];
#pragma unroll
    for (int j = 0; j < 8; j++) {
        iq[j]  = g_invQ[g * LQQ + tx8 + j];
        qmv[j] = qm[g * LQQ + tx8 + j];
    }
    int mbase = m0 + ty8;
#pragma unroll
    for (int i = 0; i < 8; i++) {
        float ic  = g_invC[g * LCC + mbase + i] * FSCALE;
        float cmv = cm[g * LCC + mbase + i];
        float* dst = g_S + ((size_t)g * LCC + mbase + i) * LQQ + tx8;
#pragma unroll
        for (int j = 0; j < 4; j += 2) {
            float2 p0 = unpack2(acc2[i][j]);
            float2 p1 = unpack2(acc2[i][j + 1]);
            float4 o;
            o.x = p0.x * ic * iq[2*j    ] - FPEN * (1.f - cmv * qmv[2*j    ]);
            o.y = p0.y * ic * iq[2*j + 1] - FPEN * (1.f - cmv * qmv[2*j + 1]);
            o.z = p1.x * ic * iq[2*j + 2] - FPEN * (1.f - cmv * qmv[2*j + 2]);
            o.w = p1.y * ic * iq[2*j + 3] - FPEN * (1.f - cmv * qmv[2*j + 3]);
            *(float4*)(dst + 2*j) = o;
        }
    }
}

// ---------------------------------------------------------------------------
// Row softmax (over Lq=128) -> P_c = softmax * c_mask * q_mask. Warp per row.
// ---------------------------------------------------------------------------
__global__ void row_softmax(const float* __restrict__ cm, const float* __restrict__ qm) {
    int row = (blockIdx.x * blockDim.x + threadIdx.x) >> 5;
    if (row >= NG * LCC) return;
    int lane = threadIdx.x & 31;
    int g = row >> 8;
    float4 v = ((const float4*)(g_S + (size_t)row * LQQ))[lane];
    float m = fmaxf(fmaxf(v.x, v.y), fmaxf(v.z, v.w));
#pragma unroll
    for (int o = 16; o; o >>= 1) m = fmaxf(m, __shfl_xor_sync(0xffffffffu, m, o));
    float e0 = __expf(v.x - m), e1 = __expf(v.y - m), e2 = __expf(v.z - m), e3 = __expf(v.w - m);
    float sum = (e0 + e1) + (e2 + e3);
#pragma unroll
    for (int o = 16; o; o >>= 1) sum += __shfl_xor_sync(0xffffffffu, sum, o);
    float inv = cm[row] / sum;   // fold c_mask into the normalizer
    float4 qv = ((const float4*)(qm + (size_t)g * LQQ))[lane];
    float4 o4;
    o4.x = e0 * inv * qv.x; o4.y = e1 * inv * qv.y;
    o4.z = e2 * inv * qv.z; o4.w = e3 * inv * qv.w;
    ((float4*)(g_Pc + (size_t)row * LQQ))[lane] = o4;
}

// ---------------------------------------------------------------------------
// Column softmax (over Lc=256) -> P_q = softmax * masks.
// ---------------------------------------------------------------------------
__global__ void col_softmax(const float* __restrict__ cm, const float* __restrict__ qm) {
    __shared__ float cms[LCC];
    int g = blockIdx.x;
    int q = threadIdx.x;
    for (int c = q; c < LCC; c += 128) cms[c] = cm[g * LCC + c];
    __syncthreads();
    const float* s = g_S + (size_t)g * LCC * LQQ + q;
    float m0 = -3e38f, m1 = -3e38f, m2 = -3e38f, m3 = -3e38f;
#pragma unroll 4
    for (int c = 0; c < LCC; c += 4) {
        m0 = fmaxf(m0, s[(c    ) * LQQ]);
        m1 = fmaxf(m1, s[(c + 1) * LQQ]);
        m2 = fmaxf(m2, s[(c + 2) * LQQ]);
        m3 = fmaxf(m3, s[(c + 3) * LQQ]);
    }
    float m = fmaxf(fmaxf(m0, m1), fmaxf(m2, m3));
    float s0 = 0.f, s1 = 0.f, s2 = 0.f, s3 = 0.f;
#pragma unroll 4
    for (int c = 0; c < LCC; c += 4) {
        s0 += __expf(s[(c    ) * LQQ] - m);
        s1 += __expf(s[(c + 1) * LQQ] - m);
        s2 += __expf(s[(c + 2) * LQQ] - m);
        s3 += __expf(s[(c + 3) * LQQ] - m);
    }
    float inv = qm[g * LQQ + q] / ((s0 + s1) + (s2 + s3));  // fold q_mask
    float* p = g_Pq + (size_t)g * LCC * LQQ + q;
#pragma unroll 4
    for (int c = 0; c < LCC; c++)
        p[c * LQQ] = __expf(s[c * LQQ] - m) * inv * cms[c];
}

// ---------------------------------------------------------------------------
// Mask outputs: S_mask [g,c,q] and S_mask^T [g,q,c].
// ---------------------------------------------------------------------------
__global__ void mask_kernel(const float* __restrict__ cm, const float* __restrict__ qm,
                            float* __restrict__ outM, float* __restrict__ outMT) {
    int i = blockIdx.x * blockDim.x + threadIdx.x;
    int g = i >> 15;
    {
        int q = i & 127, c = (i >> 7) & 255;
        outM[i] = cm[g * LCC + c] * qm[g * LQQ + q];
    }
    {
        int c = i & 255, q = (i >> 8) & 127;
        outMT[i] = cm[g * LCC + c] * qm[g * LQQ + q];
    }
}

// ---------------------------------------------------------------------------
// A_c = P_c @ Q : [256,128] x [128,512] per group. grid (4, 2, G).
// ---------------------------------------------------------------------------
__global__ __launch_bounds__(256) void gemm_Ac(const float* __restrict__ Qin,
                                               float* __restrict__ out) {
    __shared__ float As[16][132];
    __shared__ float Bs[16][132];
    int g  = blockIdx.z;
    int m0 = blockIdx.y * 128;
    int n0 = blockIdx.x * 128;
    const float* A = g_Pc + (size_t)g * LCC * LQQ;
    const float* B = Qin  + (size_t)g * LQQ * HD;
    int t = threadIdx.x;
    int tx8 = (t & 15) * 8, ty8 = (t >> 4) * 8;
    unsigned long long acc2[8][4] = {};
    for (int k0 = 0; k0 < LQQ; k0 += 16) {
#pragma unroll
        for (int i = 0; i < 2; i++) {
            int f = t + i * 256;
            int r = f >> 2; int c4 = (f & 3) << 2;
            float4 v = *(const float4*)(A + (size_t)(m0 + r) * LQQ + (k0 + c4));
            As[c4][r] = v.x; As[c4 + 1][r] = v.y; As[c4 + 2][r] = v.z; As[c4 + 3][r] = v.w;
            int kr = f >> 5; int cc = (f & 31) << 2;
            float4 w = *(const float4*)(B + (size_t)(k0 + kr) * HD + (n0 + cc));
            *(float4*)&Bs[kr][cc] = w;
        }
        __syncthreads();
        GEMM_MMA2();
        __syncthreads();
    }
#pragma unroll
    for (int i = 0; i < 8; i++) {
        float* dst = out + ((size_t)g * LCC + m0 + ty8 + i) * HD + n0 + tx8;
#pragma unroll
        for (int j = 0; j < 4; j += 2) {
            float2 p0 = unpack2(acc2[i][j]);
            float2 p1 = unpack2(acc2[i][j + 1]);
            float4 o = {p0.x, p0.y, p1.x, p1.y};
            *(float4*)(dst + 2*j) = o;
        }
    }
}

// ---------------------------------------------------------------------------
// A_q = P_q^T @ C : [128,256] x [256,512] per group. A stored [K=256][M=128].
// ---------------------------------------------------------------------------
__global__ __launch_bounds__(256) void gemm_Aq(const float* __restrict__ Cin,
                                               float* __restrict__ out) {
    __shared__ float As[16][132];
    __shared__ float Bs[16][132];
    int g  = blockIdx.z;
    int n0 = blockIdx.x * 128;
    const float* A = g_Pq + (size_t)g * LCC * LQQ;
    const float* B = Cin  + (size_t)g * LCC * HD;
    int t = threadIdx.x;
    int tx8 = (t & 15) * 8, ty8 = (t >> 4) * 8;
    unsigned long long acc2[8][4] = {};
    for (int k0 = 0; k0 < LCC; k0 += 16) {
#pragma unroll
        for (int i = 0; i < 2; i++) {
            int f = t + i * 256;
            int kr = f >> 5; int cc = (f & 31) << 2;
            float4 v = *(const float4*)(A + (size_t)(k0 + kr) * LQQ + cc);
            *(float4*)&As[kr][cc] = v;
            float4 w = *(const float4*)(B + (size_t)(k0 + kr) * HD + (n0 + cc));
            *(float4*)&Bs[kr][cc] = w;
        }
        __syncthreads();
        GEMM_MMA2();
        __syncthreads();
    }
#pragma unroll
    for (int i = 0; i < 8; i++) {
        float* dst = out + ((size_t)g * LQQ + ty8 + i) * HD + n0 + tx8;
#pragma unroll
        for (int j = 0; j < 4; j += 2) {
            float2 p0 = unpack2(acc2[i][j]);
            float2 p1 = unpack2(acc2[i][j + 1]);
            float4 o = {p0.x, p0.y, p1.x, p1.y};
            *(float4*)(dst + 2*j) = o;
        }
    }
}

// ---------------------------------------------------------------------------
extern "C" void kernel_launch(void* const* d_in, const int* in_sizes, int n_in,
                              void* d_out, int out_size) {
    const float* Cin = (const float*)d_in[0];
    const float* Qin = (const float*)d_in[1];
    const float* cm  = (const float*)d_in[2];
    const float* qm  = (const float*)d_in[3];
    float* out   = (float*)d_out;
    float* outAc = out;
    float* outAq = outAc + (size_t)NG * LCC * HD;
    float* outM  = outAq + (size_t)NG * LQQ * HD;
    float* outMT = outM  + (size_t)NG * LCC * LQQ;

    norm_kernel<<<NG * LCC / 8, 256>>>(Cin, NG * LCC, 0);
    norm_kernel<<<NG * LQQ / 8, 256>>>(Qin, NG * LQQ, 1);
    sgemm_S<<<dim3(1, 2, NG), 256>>>(Cin, Qin, cm, qm);
    row_softmax<<<NG * LCC / 8, 256>>>(cm, qm);
    col_softmax<<<NG, 128>>>(cm, qm);
    mask_kernel<<<NG * LCC * LQQ / 256, 256>>>(cm, qm, outM, outMT);
    gemm_Ac<<<dim3(4, 2, NG), 256>>>(Qin, outAc);
    gemm_Aq<<<dim3(4, 1, NG), 256>>>(Cin, outAq);
}

// round 5
// speedup vs baseline: 1.5593x; 1.5480x over previous
#include <cuda_runtime.h>
#include <cuda_bf16.h>
#include <stdint.h>
#include <math.h>

// Problem constants: B=16, X=4, I=8 -> G=512 groups; Lc=256, Lq=128, H=512
#define NG 512
#define LCC 256
#define LQQ 128
#define HD 512
#define FSCALE 100.0f
#define FPEN 1.0e12f   // NEG_BIG * SCALE

// Scratch (static device globals: allocation-free per harness rules)
__device__ float g_S [NG * LCC * LQQ];   // masked, scaled logits
__device__ float g_Pc[NG * LCC * LQQ];   // row-softmax probs * mask  [c][q]
__device__ float g_Pq[NG * LCC * LQQ];   // col-softmax probs * mask  [c][q]
__device__ float g_invC[NG * LCC];
__device__ float g_invQ[NG * LQQ];

// ---------------------------------------------------------------------------
// helpers
// ---------------------------------------------------------------------------
static __device__ __forceinline__ uint32_t smem_u32(const void* p) {
    uint32_t a;
    asm("{ .reg .u64 t; cvta.to.shared.u64 t, %1; cvt.u32.u64 %0, t; }"
        : "=r"(a) : "l"(p));
    return a;
}

// pack two floats as bf16x2 {lo, hi}
static __device__ __forceinline__ uint32_t pack_bf2(float lo, float hi) {
    uint32_t r;
    asm("cvt.rn.bf16x2.f32 %0, %1, %2;" : "=r"(r) : "f"(hi), "f"(lo));
    return r;
}

// split a float4 into bf16 hi/lo pairs and store 8B each to smem
static __device__ __forceinline__ void split_store(uint8_t* sh, uint8_t* sl,
                                                   int off, float4 v) {
    float hx = __bfloat162float(__float2bfloat16(v.x));
    float hy = __bfloat162float(__float2bfloat16(v.y));
    float hz = __bfloat162float(__float2bfloat16(v.z));
    float hw = __bfloat162float(__float2bfloat16(v.w));
    uint2 H, L;
    H.x = pack_bf2(hx, hy);
    H.y = pack_bf2(hz, hw);
    L.x = pack_bf2(v.x - hx, v.y - hy);
    L.y = pack_bf2(v.z - hz, v.w - hw);
    *(uint2*)(sh + off) = H;
    *(uint2*)(sl + off) = L;
}

static __device__ __forceinline__ void ldm4(uint32_t* r, uint32_t a) {
    asm volatile("ldmatrix.sync.aligned.m8n8.x4.shared.b16 {%0,%1,%2,%3}, [%4];"
                 : "=r"(r[0]), "=r"(r[1]), "=r"(r[2]), "=r"(r[3]) : "r"(a));
}
static __device__ __forceinline__ void ldm4t(uint32_t* r, uint32_t a) {
    asm volatile("ldmatrix.sync.aligned.m8n8.x4.trans.shared.b16 {%0,%1,%2,%3}, [%4];"
                 : "=r"(r[0]), "=r"(r[1]), "=r"(r[2]), "=r"(r[3]) : "r"(a));
}

static __device__ __forceinline__ void mma16816(float* d, const uint32_t* a,
                                                const uint32_t* b) {
    asm volatile(
        "mma.sync.aligned.m16n8k16.row.col.f32.bf16.bf16.f32 "
        "{%0,%1,%2,%3}, {%4,%5,%6,%7}, {%8,%9}, {%0,%1,%2,%3};"
        : "+f"(d[0]), "+f"(d[1]), "+f"(d[2]), "+f"(d[3])
        : "r"(a[0]), "r"(a[1]), "r"(a[2]), "r"(a[3]), "r"(b[0]), "r"(b[1]));
}

// ---------------------------------------------------------------------------
// Row L2 inverse norms. One warp per row of H=512 floats.
// ---------------------------------------------------------------------------
__global__ void norm_kernel(const float* __restrict__ X, int nrows, int sel) {
    int gw   = (blockIdx.x * blockDim.x + threadIdx.x) >> 5;
    int lane = threadIdx.x & 31;
    if (gw >= nrows) return;
    const float4* row = (const float4*)(X + (size_t)gw * HD);
    float s = 0.f;
#pragma unroll
    for (int i = 0; i < HD / 128; i++) {
        float4 v = row[lane + 32 * i];
        s = fmaf(v.x, v.x, fmaf(v.y, v.y, fmaf(v.z, v.z, fmaf(v.w, v.w, s))));
    }
#pragma unroll
    for (int o = 16; o; o >>= 1) s += __shfl_xor_sync(0xffffffffu, s, o);
    if (lane == 0) {
        float inv = 1.f / fmaxf(sqrtf(s), 1e-12f);
        if (sel) g_invQ[gw] = inv; else g_invC[gw] = inv;
    }
}

// ---------------------------------------------------------------------------
// S = (C @ Q^T) scaled/normalized/masked via HMMA bf16 hi/lo (3-MMA emulation).
// Block: 128(m) x 128(n=Lq), 8 warps (2m x 4n), BK=32. TN layout (both K-major).
// ---------------------------------------------------------------------------
__global__ __launch_bounds__(256) void sgemm_S(
    const float* __restrict__ Cin, const float* __restrict__ Qin,
    const float* __restrict__ cm, const float* __restrict__ qm) {
    __shared__ __align__(16) uint8_t sm[40960];   // Ah,Al,Bh,Bl: 128x32 bf16 @80B
    __shared__ float s_iq[LQQ], s_qm[LQQ];
    uint8_t* Ah = sm;
    uint8_t* Al = sm + 10240;
    uint8_t* Bh = sm + 20480;
    uint8_t* Bl = sm + 30720;
    int t = threadIdx.x, lane = t & 31, wid = t >> 5;
    int wm = wid & 1, wn = wid >> 1;
    int g = blockIdx.y, m0 = blockIdx.x * 128;
    if (t < LQQ) { s_iq[t] = g_invQ[g * LQQ + t]; s_qm[t] = qm[g * LQQ + t]; }
    const float* Ag = Cin + (size_t)(g * LCC + m0) * HD;
    const float* Bg = Qin + (size_t)g * LQQ * HD;
    float acc[4][4][4] = {};
    for (int kc = 0; kc < HD / 32; kc++) {
#pragma unroll
        for (int i = 0; i < 4; i++) {
            int idx = t + i * 256;
            int r = idx >> 3, c = idx & 7;           // 128 rows x 8 float4
            float4 v = *(const float4*)(Ag + (size_t)r * HD + kc * 32 + c * 4);
            split_store(Ah, Al, r * 80 + c * 8, v);
            float4 w = *(const float4*)(Bg + (size_t)r * HD + kc * 32 + c * 4);
            split_store(Bh, Bl, r * 80 + c * 8, w);
        }
        __syncthreads();
#pragma unroll
        for (int k16 = 0; k16 < 2; k16++) {
            uint32_t ah[4][4], al[4][4], bh[4][2], bl[4][2];
            int colb = k16 * 32 + ((lane >> 4) & 1) * 16;
            int ra = wm * 64 + (lane & 15);
#pragma unroll
            for (int fm = 0; fm < 4; fm++) {
                ldm4(ah[fm], smem_u32(Ah + (ra + fm * 16) * 80 + colb));
                ldm4(al[fm], smem_u32(Al + (ra + fm * 16) * 80 + colb));
            }
            int rb = wn * 32 + (lane & 15);
#pragma unroll
            for (int bg = 0; bg < 2; bg++) {
                uint32_t r4[4];
                ldm4(r4, smem_u32(Bh + (rb + bg * 16) * 80 + colb));
                bh[bg * 2][0] = r4[0]; bh[bg * 2][1] = r4[2];
                bh[bg * 2 + 1][0] = r4[1]; bh[bg * 2 + 1][1] = r4[3];
                ldm4(r4, smem_u32(Bl + (rb + bg * 16) * 80 + colb));
                bl[bg * 2][0] = r4[0]; bl[bg * 2][1] = r4[2];
                bl[bg * 2 + 1][0] = r4[1]; bl[bg * 2 + 1][1] = r4[3];
            }
#pragma unroll
            for (int fm = 0; fm < 4; fm++)
#pragma unroll
                for (int ni = 0; ni < 4; ni++) {
                    mma16816(acc[fm][ni], ah[fm], bh[ni]);
                    mma16816(acc[fm][ni], ah[fm], bl[ni]);
                    mma16816(acc[fm][ni], al[fm], bh[ni]);
                }
        }
        __syncthreads();
    }
    int g2 = lane >> 2, t4 = lane & 3;
#pragma unroll
    for (int fm = 0; fm < 4; fm++)
#pragma unroll
        for (int half = 0; half < 2; half++) {
            int row = m0 + wm * 64 + fm * 16 + g2 + half * 8;
            float ic = g_invC[g * LCC + row] * FSCALE;
            float cv = cm[g * LCC + row];
            float* dst = g_S + ((size_t)g * LCC + row) * LQQ;
#pragma unroll
            for (int ni = 0; ni < 4; ni++) {
                int col = wn * 32 + ni * 8 + t4 * 2;
                float2 o;
                o.x = acc[fm][ni][half * 2    ] * ic * s_iq[col    ] - FPEN * (1.f - cv * s_qm[col    ]);
                o.y = acc[fm][ni][half * 2 + 1] * ic * s_iq[col + 1] - FPEN * (1.f - cv * s_qm[col + 1]);
                *(float2*)(dst + col) = o;
            }
        }
}

// ---------------------------------------------------------------------------
// NN GEMM via HMMA bf16 hi/lo: out[M,512] = A[M,K] @ B[K,512] per group.
// ATRANS=false: A = g_Pc (row-major [m][k]);  Ac: M=256, K=128.
// ATRANS=true : A = g_Pq (stored [k=c][m=q]); Aq: M=128, K=256 (A^T product).
// B (Q or C) is [K][512] row-major -> ldmatrix.trans.
// ---------------------------------------------------------------------------
template<bool ATRANS>
__global__ __launch_bounds__(256) void nn_gemm(const float* __restrict__ Bg0,
                                               float* __restrict__ out,
                                               int M, int K) {
    constexpr int ASZ = ATRANS ? 8704 : 10240;
    __shared__ __align__(16) uint8_t sm[2 * ASZ + 2 * 8704];
    uint8_t* Ah = sm;
    uint8_t* Al = sm + ASZ;
    uint8_t* Bh = sm + 2 * ASZ;
    uint8_t* Bl = sm + 2 * ASZ + 8704;
    int t = threadIdx.x, lane = t & 31, wid = t >> 5;
    int wm = wid & 1, wn = wid >> 1;
    int g = blockIdx.z, m0 = blockIdx.y * 128, n0 = blockIdx.x * 128;
    const float* Ag = (ATRANS ? g_Pq : g_Pc) + (size_t)g * LCC * LQQ;
    const float* Bg = Bg0 + (size_t)g * K * HD;
    float acc[4][4][4] = {};
    int KCH = K >> 5;
    for (int kc = 0; kc < KCH; kc++) {
#pragma unroll
        for (int i = 0; i < 4; i++) {
            int idx = t + i * 256;
            if (!ATRANS) {
                int r = idx >> 3, c = idx & 7;       // 128 rows x 8 float4
                float4 v = *(const float4*)(Ag + (size_t)(m0 + r) * K + kc * 32 + c * 4);
                split_store(Ah, Al, r * 80 + c * 8, v);
            } else {
                int kr = idx >> 5, c = idx & 31;     // 32 k-rows x 32 float4
                float4 v = *(const float4*)(Ag + (size_t)(kc * 32 + kr) * M + c * 4);
                split_store(Ah, Al, kr * 272 + c * 8, v);
            }
            {
                int kr = idx >> 5, c = idx & 31;     // 32 k-rows x 32 float4
                float4 v = *(const float4*)(Bg + (size_t)(kc * 32 + kr) * HD + n0 + c * 4);
                split_store(Bh, Bl, kr * 272 + c * 8, v);
            }
        }
        __syncthreads();
#pragma unroll
        for (int k16 = 0; k16 < 2; k16++) {
            uint32_t ah[4][4], al[4][4], bh[4][2], bl[4][2];
            if (!ATRANS) {
                int colb = k16 * 32 + ((lane >> 4) & 1) * 16;
                int ra = wm * 64 + (lane & 15);
#pragma unroll
                for (int fm = 0; fm < 4; fm++) {
                    ldm4(ah[fm], smem_u32(Ah + (ra + fm * 16) * 80 + colb));
                    ldm4(al[fm], smem_u32(Al + (ra + fm * 16) * 80 + colb));
                }
            } else {
                int row = k16 * 16 + (lane & 7) + ((lane >> 4) & 1) * 8;
                int cb  = wm * 128 + ((lane >> 3) & 1) * 16;
#pragma unroll
                for (int fm = 0; fm < 4; fm++) {
                    ldm4t(ah[fm], smem_u32(Ah + row * 272 + cb + fm * 32));
                    ldm4t(al[fm], smem_u32(Al + row * 272 + cb + fm * 32));
                }
            }
            {
                int rowb = k16 * 16 + (lane & 7) + ((lane >> 3) & 1) * 8;
                int cbb  = wn * 64 + ((lane >> 4) & 1) * 16;
#pragma unroll
                for (int bg = 0; bg < 2; bg++) {
                    uint32_t r4[4];
                    ldm4t(r4, smem_u32(Bh + rowb * 272 + cbb + bg * 32));
                    bh[bg * 2][0] = r4[0]; bh[bg * 2][1] = r4[1];
                    bh[bg * 2 + 1][0] = r4[2]; bh[bg * 2 + 1][1] = r4[3];
                    ldm4t(r4, smem_u32(Bl + rowb * 272 + cbb + bg * 32));
                    bl[bg * 2][0] = r4[0]; bl[bg * 2][1] = r4[1];
                    bl[bg * 2 + 1][0] = r4[2]; bl[bg * 2 + 1][1] = r4[3];
                }
            }
#pragma unroll
            for (int fm = 0; fm < 4; fm++)
#pragma unroll
                for (int ni = 0; ni < 4; ni++) {
                    mma16816(acc[fm][ni], ah[fm], bh[ni]);
                    mma16816(acc[fm][ni], ah[fm], bl[ni]);
                    mma16816(acc[fm][ni], al[fm], bh[ni]);
                }
        }
        __syncthreads();
    }
    int g2 = lane >> 2, t4 = lane & 3;
#pragma unroll
    for (int fm = 0; fm < 4; fm++)
#pragma unroll
        for (int half = 0; half < 2; half++) {
            int row = m0 + wm * 64 + fm * 16 + g2 + half * 8;
            float* dst = out + ((size_t)g * M + row) * HD + n0;
#pragma unroll
            for (int ni = 0; ni < 4; ni++) {
                int col = wn * 32 + ni * 8 + t4 * 2;
                float2 o = {acc[fm][ni][half * 2], acc[fm][ni][half * 2 + 1]};
                *(float2*)(dst + col) = o;
            }
        }
}

// ---------------------------------------------------------------------------
// Row softmax (over Lq=128) -> P_c = softmax * c_mask * q_mask. Warp per row.
// ---------------------------------------------------------------------------
__global__ void row_softmax(const float* __restrict__ cm, const float* __restrict__ qm) {
    int row = (blockIdx.x * blockDim.x + threadIdx.x) >> 5;
    if (row >= NG * LCC) return;
    int lane = threadIdx.x & 31;
    int g = row >> 8;
    float4 v = ((const float4*)(g_S + (size_t)row * LQQ))[lane];
    float m = fmaxf(fmaxf(v.x, v.y), fmaxf(v.z, v.w));
#pragma unroll
    for (int o = 16; o; o >>= 1) m = fmaxf(m, __shfl_xor_sync(0xffffffffu, m, o));
    float e0 = __expf(v.x - m), e1 = __expf(v.y - m), e2 = __expf(v.z - m), e3 = __expf(v.w - m);
    float sum = (e0 + e1) + (e2 + e3);
#pragma unroll
    for (int o = 16; o; o >>= 1) sum += __shfl_xor_sync(0xffffffffu, sum, o);
    float inv = cm[row] / sum;   // fold c_mask into the normalizer
    float4 qv = ((const float4*)(qm + (size_t)g * LQQ))[lane];
    float4 o4;
    o4.x = e0 * inv * qv.x; o4.y = e1 * inv * qv.y;
    o4.z = e2 * inv * qv.z; o4.w = e3 * inv * qv.w;
    ((float4*)(g_Pc + (size_t)row * LQQ))[lane] = o4;
}

// ---------------------------------------------------------------------------
// Column softmax (over Lc=256) -> P_q = softmax * masks. Stored [c][q].
// ---------------------------------------------------------------------------
__global__ void col_softmax(const float* __restrict__ cm, const float* __restrict__ qm) {
    __shared__ float cms[LCC];
    int g = blockIdx.x;
    int q = threadIdx.x;
    for (int c = q; c < LCC; c += 128) cms[c] = cm[g * LCC + c];
    __syncthreads();
    const float* s = g_S + (size_t)g * LCC * LQQ + q;
    float m0 = -3e38f, m1 = -3e38f, m2 = -3e38f, m3 = -3e38f;
#pragma unroll 4
    for (int c = 0; c < LCC; c += 4) {
        m0 = fmaxf(m0, s[(c    ) * LQQ]);
        m1 = fmaxf(m1, s[(c + 1) * LQQ]);
        m2 = fmaxf(m2, s[(c + 2) * LQQ]);
        m3 = fmaxf(m3, s[(c + 3) * LQQ]);
    }
    float m = fmaxf(fmaxf(m0, m1), fmaxf(m2, m3));
    float s0 = 0.f, s1 = 0.f, s2 = 0.f, s3 = 0.f;
#pragma unroll 4
    for (int c = 0; c < LCC; c += 4) {
        s0 += __expf(s[(c    ) * LQQ] - m);
        s1 += __expf(s[(c + 1) * LQQ] - m);
        s2 += __expf(s[(c + 2) * LQQ] - m);
        s3 += __expf(s[(c + 3) * LQQ] - m);
    }
    float inv = qm[g * LQQ + q] / ((s0 + s1) + (s2 + s3));  // fold q_mask
    float* p = g_Pq + (size_t)g * LCC * LQQ + q;
#pragma unroll 4
    for (int c = 0; c < LCC; c++)
        p[c * LQQ] = __expf(s[c * LQQ] - m) * inv * cms[c];
}

// ---------------------------------------------------------------------------
// Mask outputs: S_mask [g,c,q] and S_mask^T [g,q,c].
// ---------------------------------------------------------------------------
__global__ void mask_kernel(const float* __restrict__ cm, const float* __restrict__ qm,
                            float* __restrict__ outM, float* __restrict__ outMT) {
    int i = blockIdx.x * blockDim.x + threadIdx.x;
    int g = i >> 15;
    {
        int q = i & 127, c = (i >> 7) & 255;
        outM[i] = cm[g * LCC + c] * qm[g * LQQ + q];
    }
    {
        int c = i & 255, q = (i >> 8) & 127;
        outMT[i] = cm[g * LCC + c] * qm[g * LQQ + q];
    }
}

// ---------------------------------------------------------------------------
extern "C" void kernel_launch(void* const* d_in, const int* in_sizes, int n_in,
                              void* d_out, int out_size) {
    const float* Cin = (const float*)d_in[0];
    const float* Qin = (const float*)d_in[1];
    const float* cm  = (const float*)d_in[2];
    const float* qm  = (const float*)d_in[3];
    float* out   = (float*)d_out;
    float* outAc = out;
    float* outAq = outAc + (size_t)NG * LCC * HD;
    float* outM  = outAq + (size_t)NG * LQQ * HD;
    float* outMT = outM  + (size_t)NG * LCC * LQQ;

    norm_kernel<<<NG * LCC / 8, 256>>>(Cin, NG * LCC, 0);
    norm_kernel<<<NG * LQQ / 8, 256>>>(Qin, NG * LQQ, 1);
    sgemm_S<<<dim3(2, NG), 256>>>(Cin, Qin, cm, qm);
    row_softmax<<<NG * LCC / 8, 256>>>(cm, qm);
    col_softmax<<<NG, 128>>>(cm, qm);
    mask_kernel<<<NG * LCC * LQQ / 256, 256>>>(cm, qm, outM, outMT);
    nn_gemm<false><<<dim3(4, 2, NG), 256>>>(Qin, outAc, LCC, LQQ);
    nn_gemm<true ><<<dim3(4, 1, NG), 256>>>(Cin, outAq, LQQ, LCC);
}

// round 6
// speedup vs baseline: 1.6947x; 1.0868x over previous
#include <cuda_runtime.h>
#include <cuda_bf16.h>
#include <stdint.h>
#include <math.h>

// Problem constants: B=16, X=4, I=8 -> G=512 groups; Lc=256, Lq=128, H=512
#define NG 512
#define LCC 256
#define LQQ 128
#define HD 512
#define FSCALE 100.0f
#define FPEN 1.0e12f   // NEG_BIG * SCALE

// Scratch (static device globals: allocation-free per harness rules)
__device__ float g_Pc[NG * LCC * LQQ];   // row-softmax probs * mask  [c][q]
__device__ float g_Pq[NG * LCC * LQQ];   // col-softmax probs * mask  [c][q]
__device__ float g_invC[NG * LCC];
__device__ float g_invQ[NG * LQQ];

// ---------------------------------------------------------------------------
// helpers
// ---------------------------------------------------------------------------
static __device__ __forceinline__ uint32_t smem_u32(const void* p) {
    uint32_t a;
    asm("{ .reg .u64 t; cvta.to.shared.u64 t, %1; cvt.u32.u64 %0, t; }"
        : "=r"(a) : "l"(p));
    return a;
}

// pack two floats as bf16x2 {lo, hi}
static __device__ __forceinline__ uint32_t pack_bf2(float lo, float hi) {
    uint32_t r;
    asm("cvt.rn.bf16x2.f32 %0, %1, %2;" : "=r"(r) : "f"(hi), "f"(lo));
    return r;
}

// split a float4 into bf16 hi/lo pairs and store 8B each to smem
static __device__ __forceinline__ void split_store(uint8_t* sh, uint8_t* sl,
                                                   int off, float4 v) {
    float hx = __bfloat162float(__float2bfloat16(v.x));
    float hy = __bfloat162float(__float2bfloat16(v.y));
    float hz = __bfloat162float(__float2bfloat16(v.z));
    float hw = __bfloat162float(__float2bfloat16(v.w));
    uint2 H, L;
    H.x = pack_bf2(hx, hy);
    H.y = pack_bf2(hz, hw);
    L.x = pack_bf2(v.x - hx, v.y - hy);
    L.y = pack_bf2(v.z - hz, v.w - hw);
    *(uint2*)(sh + off) = H;
    *(uint2*)(sl + off) = L;
}

static __device__ __forceinline__ void ldm4(uint32_t* r, uint32_t a) {
    asm volatile("ldmatrix.sync.aligned.m8n8.x4.shared.b16 {%0,%1,%2,%3}, [%4];"
                 : "=r"(r[0]), "=r"(r[1]), "=r"(r[2]), "=r"(r[3]) : "r"(a));
}
static __device__ __forceinline__ void ldm4t(uint32_t* r, uint32_t a) {
    asm volatile("ldmatrix.sync.aligned.m8n8.x4.trans.shared.b16 {%0,%1,%2,%3}, [%4];"
                 : "=r"(r[0]), "=r"(r[1]), "=r"(r[2]), "=r"(r[3]) : "r"(a));
}

static __device__ __forceinline__ void mma16816(float* d, const uint32_t* a,
                                                const uint32_t* b) {
    asm volatile(
        "mma.sync.aligned.m16n8k16.row.col.f32.bf16.bf16.f32 "
        "{%0,%1,%2,%3}, {%4,%5,%6,%7}, {%8,%9}, {%0,%1,%2,%3};"
        : "+f"(d[0]), "+f"(d[1]), "+f"(d[2]), "+f"(d[3])
        : "r"(a[0]), "r"(a[1]), "r"(a[2]), "r"(a[3]), "r"(b[0]), "r"(b[1]));
}

// ---------------------------------------------------------------------------
// Row L2 inverse norms. One warp per row of H=512 floats.
// ---------------------------------------------------------------------------
__global__ void norm_kernel(const float* __restrict__ X, int nrows, int sel) {
    int gw   = (blockIdx.x * blockDim.x + threadIdx.x) >> 5;
    int lane = threadIdx.x & 31;
    if (gw >= nrows) return;
    const float4* row = (const float4*)(X + (size_t)gw * HD);
    float s = 0.f;
#pragma unroll
    for (int i = 0; i < HD / 128; i++) {
        float4 v = row[lane + 32 * i];
        s = fmaf(v.x, v.x, fmaf(v.y, v.y, fmaf(v.z, v.z, fmaf(v.w, v.w, s))));
    }
#pragma unroll
    for (int o = 16; o; o >>= 1) s += __shfl_xor_sync(0xffffffffu, s, o);
    if (lane == 0) {
        float inv = 1.f / fmaxf(sqrtf(s), 1e-12f);
        if (sel) g_invQ[gw] = inv; else g_invC[gw] = inv;
    }
}

// ---------------------------------------------------------------------------
// Fused: S = masked scaled cosine logits (HMMA bf16 hi/lo) for the WHOLE group
// (256x128) kept in smem, then row softmax -> g_Pc, col softmax -> g_Pq,
// plus both mask outputs. One CTA per group, 512 threads (16 warps, 4m x 4n).
// ---------------------------------------------------------------------------
// smem offsets (bytes)
#define OFF_S      0
#define SSTRIDE    132                       // floats; keeps float4 alignment
#define OFF_AH     (256 * SSTRIDE * 4)       // 135168
#define OFF_AL     (OFF_AH + 20480)
#define OFF_BH     (OFF_AL + 20480)
#define OFF_BL     (OFF_BH + 10240)
#define OFF_IC     (OFF_BL + 10240)          // 256 f
#define OFF_CM     (OFF_IC + 1024)           // 256 f
#define OFF_IQ     (OFF_CM + 1024)           // 128 f
#define OFF_QM     (OFF_IQ + 512)            // 128 f
#define OFF_RMAX   (OFF_QM + 512)            // 256 f
#define OFF_RINV   (OFF_RMAX + 1024)         // 256 f
#define OFF_CMAX   (OFF_RINV + 1024)         // 128 f
#define OFF_CINV   (OFF_CMAX + 512)          // 128 f
#define OFF_PM     (OFF_CINV + 512)          // 4*128 f
#define OFF_PS     (OFF_PM + 2048)           // 4*128 f
#define SMEM_FUSED (OFF_PS + 2048)           // 206848 bytes

__global__ __launch_bounds__(512, 1) void fused_S(
    const float* __restrict__ Cin, const float* __restrict__ Qin,
    const float* __restrict__ cm, const float* __restrict__ qm,
    float* __restrict__ outM, float* __restrict__ outMT) {
    extern __shared__ __align__(16) uint8_t dsm[];
    float* S      = (float*)(dsm + OFF_S);
    uint8_t* Ah   = dsm + OFF_AH;
    uint8_t* Al   = dsm + OFF_AL;
    uint8_t* Bh   = dsm + OFF_BH;
    uint8_t* Bl   = dsm + OFF_BL;
    float* s_ic   = (float*)(dsm + OFF_IC);
    float* s_cm   = (float*)(dsm + OFF_CM);
    float* s_iq   = (float*)(dsm + OFF_IQ);
    float* s_qm   = (float*)(dsm + OFF_QM);
    float* rowmax = (float*)(dsm + OFF_RMAX);
    float* rowinv = (float*)(dsm + OFF_RINV);
    float* colmax = (float*)(dsm + OFF_CMAX);
    float* colinv = (float*)(dsm + OFF_CINV);
    float* pm     = (float*)(dsm + OFF_PM);
    float* ps     = (float*)(dsm + OFF_PS);

    int t = threadIdx.x, lane = t & 31, wid = t >> 5;
    int wm = wid & 3, wn = wid >> 2;
    int g = blockIdx.x;
    if (t < 256) { s_ic[t] = g_invC[g * LCC + t] * FSCALE; s_cm[t] = cm[g * LCC + t]; }
    else if (t < 384) { int q = t - 256; s_iq[q] = g_invQ[g * LQQ + q]; s_qm[q] = qm[g * LQQ + q]; }
    const float* Ag = Cin + (size_t)g * LCC * HD;
    const float* Bg = Qin + (size_t)g * LQQ * HD;
    __syncthreads();

    // ---- mask outputs (independent of GEMM) ----
    {
        float* oM = outM + (size_t)g * LCC * LQQ;
#pragma unroll
        for (int i = 0; i < 16; i++) {
            int base = (i * 512 + t) * 4;
            int r = base >> 7, c = base & 127;
            float cv = s_cm[r];
            float4 o = {cv * s_qm[c], cv * s_qm[c + 1], cv * s_qm[c + 2], cv * s_qm[c + 3]};
            *(float4*)(oM + base) = o;
        }
        float* oT = outMT + (size_t)g * LCC * LQQ;
#pragma unroll
        for (int i = 0; i < 16; i++) {
            int base = (i * 512 + t) * 4;
            int r = base >> 8, c = base & 255;
            float qv = s_qm[r];
            float4 o = {qv * s_cm[c], qv * s_cm[c + 1], qv * s_cm[c + 2], qv * s_cm[c + 3]};
            *(float4*)(oT + base) = o;
        }
    }

    // ---- K loop: 16 chunks of BK=32 ----
    float acc[4][4][4] = {};
    for (int kc = 0; kc < 16; kc++) {
#pragma unroll
        for (int i = 0; i < 4; i++) {           // A: 256x32
            int idx = t + i * 512;
            int r = idx >> 3, c = idx & 7;
            float4 v = *(const float4*)(Ag + (size_t)r * HD + kc * 32 + c * 4);
            split_store(Ah, Al, r * 80 + c * 8, v);
        }
#pragma unroll
        for (int i = 0; i < 2; i++) {           // B: 128x32
            int idx = t + i * 512;
            int r = idx >> 3, c = idx & 7;
            float4 v = *(const float4*)(Bg + (size_t)r * HD + kc * 32 + c * 4);
            split_store(Bh, Bl, r * 80 + c * 8, v);
        }
        __syncthreads();
#pragma unroll
        for (int k16 = 0; k16 < 2; k16++) {
            uint32_t af[4][4], bh[4][2], bl[4][2];
            int colb = k16 * 32 + ((lane >> 4) & 1) * 16;
            int ra = wm * 64 + (lane & 15);
            int rb = wn * 32 + (lane & 15);
#pragma unroll
            for (int bg2 = 0; bg2 < 2; bg2++) {
                uint32_t r4[4];
                ldm4(r4, smem_u32(Bh + (rb + bg2 * 16) * 80 + colb));
                bh[bg2 * 2][0] = r4[0]; bh[bg2 * 2][1] = r4[2];
                bh[bg2 * 2 + 1][0] = r4[1]; bh[bg2 * 2 + 1][1] = r4[3];
                ldm4(r4, smem_u32(Bl + (rb + bg2 * 16) * 80 + colb));
                bl[bg2 * 2][0] = r4[0]; bl[bg2 * 2][1] = r4[2];
                bl[bg2 * 2 + 1][0] = r4[1]; bl[bg2 * 2 + 1][1] = r4[3];
            }
#pragma unroll
            for (int fm = 0; fm < 4; fm++)
                ldm4(af[fm], smem_u32(Ah + (ra + fm * 16) * 80 + colb));
#pragma unroll
            for (int fm = 0; fm < 4; fm++)
#pragma unroll
                for (int ni = 0; ni < 4; ni++) {
                    mma16816(acc[fm][ni], af[fm], bh[ni]);
                    mma16816(acc[fm][ni], af[fm], bl[ni]);
                }
#pragma unroll
            for (int fm = 0; fm < 4; fm++)
                ldm4(af[fm], smem_u32(Al + (ra + fm * 16) * 80 + colb));
#pragma unroll
            for (int fm = 0; fm < 4; fm++)
#pragma unroll
                for (int ni = 0; ni < 4; ni++)
                    mma16816(acc[fm][ni], af[fm], bh[ni]);
        }
        __syncthreads();
    }

    // ---- logits -> S smem ----
    int g2 = lane >> 2, t4 = lane & 3;
#pragma unroll
    for (int fm = 0; fm < 4; fm++)
#pragma unroll
        for (int half = 0; half < 2; half++) {
            int row = wm * 64 + fm * 16 + g2 + half * 8;
            float ic = s_ic[row], cv = s_cm[row];
#pragma unroll
            for (int ni = 0; ni < 4; ni++) {
                int col = wn * 32 + ni * 8 + t4 * 2;
                S[row * SSTRIDE + col]     = acc[fm][ni][half * 2]     * ic * s_iq[col]     - FPEN * (1.f - cv * s_qm[col]);
                S[row * SSTRIDE + col + 1] = acc[fm][ni][half * 2 + 1] * ic * s_iq[col + 1] - FPEN * (1.f - cv * s_qm[col + 1]);
            }
        }
    __syncthreads();

    // ---- row softmax stats (rotate col by lane to avoid bank conflicts) ----
    if (t < 256) {
        const float* sr = S + t * SSTRIDE;
        float m = -3.0e38f;
#pragma unroll 8
        for (int cc = 0; cc < 128; cc++) m = fmaxf(m, sr[(cc + lane) & 127]);
        float s = 0.f;
#pragma unroll 8
        for (int cc = 0; cc < 128; cc++) s += __expf(sr[(cc + lane) & 127] - m);
        rowmax[t] = m;
        rowinv[t] = s_cm[t] / s;
    }
    // ---- col partial stats ----
    {
        int c = t & 127, part = t >> 7;
        const float* sc = S + (part * 64) * SSTRIDE + c;
        float m = -3.0e38f;
#pragma unroll 8
        for (int r2 = 0; r2 < 64; r2++) m = fmaxf(m, sc[r2 * SSTRIDE]);
        float s = 0.f;
#pragma unroll 8
        for (int r2 = 0; r2 < 64; r2++) s += __expf(sc[r2 * SSTRIDE] - m);
        pm[part * 128 + c] = m;
        ps[part * 128 + c] = s;
    }
    __syncthreads();
    if (t < 128) {
        float M = fmaxf(fmaxf(pm[t], pm[128 + t]), fmaxf(pm[256 + t], pm[384 + t]));
        float T = ps[t] * __expf(pm[t] - M) + ps[128 + t] * __expf(pm[128 + t] - M)
                + ps[256 + t] * __expf(pm[256 + t] - M) + ps[384 + t] * __expf(pm[384 + t] - M);
        colmax[t] = M;
        colinv[t] = s_qm[t] / T;
    }
    __syncthreads();

    // ---- write P_c and P_q ----
    float* Pc = g_Pc + (size_t)g * LCC * LQQ;
    float* Pq = g_Pq + (size_t)g * LCC * LQQ;
#pragma unroll
    for (int i = 0; i < 16; i++) {
        int base = (i * 512 + t) * 4;
        int r = base >> 7, c = base & 127;
        float4 v = *(const float4*)(S + r * SSTRIDE + c);
        float rm = rowmax[r], ri = rowinv[r], cv = s_cm[r];
        float4 pc, pq;
        pc.x = __expf(v.x - rm) * ri * s_qm[c];
        pc.y = __expf(v.y - rm) * ri * s_qm[c + 1];
        pc.z = __expf(v.z - rm) * ri * s_qm[c + 2];
        pc.w = __expf(v.w - rm) * ri * s_qm[c + 3];
        pq.x = __expf(v.x - colmax[c])     * colinv[c]     * cv;
        pq.y = __expf(v.y - colmax[c + 1]) * colinv[c + 1] * cv;
        pq.z = __expf(v.z - colmax[c + 2]) * colinv[c + 2] * cv;
        pq.w = __expf(v.w - colmax[c + 3]) * colinv[c + 3] * cv;
        *(float4*)(Pc + base) = pc;
        *(float4*)(Pq + base) = pq;
    }
}

// ---------------------------------------------------------------------------
// NN GEMM via HMMA bf16 hi/lo: out[M,512] = A[M,K] @ B[K,512] per group.
// ATRANS=false: A = g_Pc (row-major [m][k]);  Ac: M=256, K=128.
// ATRANS=true : A = g_Pq (stored [k=c][m=q]); Aq: M=128, K=256 (A^T product).
// B (Q or C) is [K][512] row-major -> ldmatrix.trans.
// ---------------------------------------------------------------------------
template<bool ATRANS>
__global__ __launch_bounds__(256) void nn_gemm(const float* __restrict__ Bg0,
                                               float* __restrict__ out,
                                               int M, int K) {
    constexpr int ASZ = ATRANS ? 8704 : 10240;
    __shared__ __align__(16) uint8_t sm[2 * ASZ + 2 * 8704];
    uint8_t* Ah = sm;
    uint8_t* Al = sm + ASZ;
    uint8_t* Bh = sm + 2 * ASZ;
    uint8_t* Bl = sm + 2 * ASZ + 8704;
    int t = threadIdx.x, lane = t & 31, wid = t >> 5;
    int wm = wid & 1, wn = wid >> 1;
    int g = blockIdx.z, m0 = blockIdx.y * 128, n0 = blockIdx.x * 128;
    const float* Ag = (ATRANS ? g_Pq : g_Pc) + (size_t)g * LCC * LQQ;
    const float* Bg = Bg0 + (size_t)g * K * HD;
    float acc[4][4][4] = {};
    int KCH = K >> 5;
    for (int kc = 0; kc < KCH; kc++) {
#pragma unroll
        for (int i = 0; i < 4; i++) {
            int idx = t + i * 256;
            if (!ATRANS) {
                int r = idx >> 3, c = idx & 7;       // 128 rows x 8 float4
                float4 v = *(const float4*)(Ag + (size_t)(m0 + r) * K + kc * 32 + c * 4);
                split_store(Ah, Al, r * 80 + c * 8, v);
            } else {
                int kr = idx >> 5, c = idx & 31;     // 32 k-rows x 32 float4
                float4 v = *(const float4*)(Ag + (size_t)(kc * 32 + kr) * M + c * 4);
                split_store(Ah, Al, kr * 272 + c * 8, v);
            }
            {
                int kr = idx >> 5, c = idx & 31;     // 32 k-rows x 32 float4
                float4 v = *(const float4*)(Bg + (size_t)(kc * 32 + kr) * HD + n0 + c * 4);
                split_store(Bh, Bl, kr * 272 + c * 8, v);
            }
        }
        __syncthreads();
#pragma unroll
        for (int k16 = 0; k16 < 2; k16++) {
            uint32_t ah[4][4], al[4][4], bh[4][2], bl[4][2];
            if (!ATRANS) {
                int colb = k16 * 32 + ((lane >> 4) & 1) * 16;
                int ra = wm * 64 + (lane & 15);
#pragma unroll
                for (int fm = 0; fm < 4; fm++) {
                    ldm4(ah[fm], smem_u32(Ah + (ra + fm * 16) * 80 + colb));
                    ldm4(al[fm], smem_u32(Al + (ra + fm * 16) * 80 + colb));
                }
            } else {
                int row = k16 * 16 + (lane & 7) + ((lane >> 4) & 1) * 8;
                int cb  = wm * 128 + ((lane >> 3) & 1) * 16;
#pragma unroll
                for (int fm = 0; fm < 4; fm++) {
                    ldm4t(ah[fm], smem_u32(Ah + row * 272 + cb + fm * 32));
                    ldm4t(al[fm], smem_u32(Al + row * 272 + cb + fm * 32));
                }
            }
            {
                int rowb = k16 * 16 + (lane & 7) + ((lane >> 3) & 1) * 8;
                int cbb  = wn * 64 + ((lane >> 4) & 1) * 16;
#pragma unroll
                for (int bg = 0; bg < 2; bg++) {
                    uint32_t r4[4];
                    ldm4t(r4, smem_u32(Bh + rowb * 272 + cbb + bg * 32));
                    bh[bg * 2][0] = r4[0]; bh[bg * 2][1] = r4[1];
                    bh[bg * 2 + 1][0] = r4[2]; bh[bg * 2 + 1][1] = r4[3];
                    ldm4t(r4, smem_u32(Bl + rowb * 272 + cbb + bg * 32));
                    bl[bg * 2][0] = r4[0]; bl[bg * 2][1] = r4[1];
                    bl[bg * 2 + 1][0] = r4[2]; bl[bg * 2 + 1][1] = r4[3];
                }
            }
#pragma unroll
            for (int fm = 0; fm < 4; fm++)
#pragma unroll
                for (int ni = 0; ni < 4; ni++) {
                    mma16816(acc[fm][ni], ah[fm], bh[ni]);
                    mma16816(acc[fm][ni], ah[fm], bl[ni]);
                    mma16816(acc[fm][ni], al[fm], bh[ni]);
                }
        }
        __syncthreads();
    }
    int g2 = lane >> 2, t4 = lane & 3;
#pragma unroll
    for (int fm = 0; fm < 4; fm++)
#pragma unroll
        for (int half = 0; half < 2; half++) {
            int row = m0 + wm * 64 + fm * 16 + g2 + half * 8;
            float* dst = out + ((size_t)g * M + row) * HD + n0;
#pragma unroll
            for (int ni = 0; ni < 4; ni++) {
                int col = wn * 32 + ni * 8 + t4 * 2;
                float2 o = {acc[fm][ni][half * 2], acc[fm][ni][half * 2 + 1]};
                *(float2*)(dst + col) = o;
            }
        }
}

// ---------------------------------------------------------------------------
extern "C" void kernel_launch(void* const* d_in, const int* in_sizes, int n_in,
                              void* d_out, int out_size) {
    const float* Cin = (const float*)d_in[0];
    const float* Qin = (const float*)d_in[1];
    const float* cm  = (const float*)d_in[2];
    const float* qm  = (const float*)d_in[3];
    float* out   = (float*)d_out;
    float* outAc = out;
    float* outAq = outAc + (size_t)NG * LCC * HD;
    float* outM  = outAq + (size_t)NG * LQQ * HD;
    float* outMT = outM  + (size_t)NG * LCC * LQQ;

    cudaFuncSetAttribute(fused_S, cudaFuncAttributeMaxDynamicSharedMemorySize,
                         SMEM_FUSED);

    norm_kernel<<<NG * LCC / 8, 256>>>(Cin, NG * LCC, 0);
    norm_kernel<<<NG * LQQ / 8, 256>>>(Qin, NG * LQQ, 1);
    fused_S<<<NG, 512, SMEM_FUSED>>>(Cin, Qin, cm, qm, outM, outMT);
    nn_gemm<false><<<dim3(4, 2, NG), 256>>>(Qin, outAc, LCC, LQQ);
    nn_gemm<true ><<<dim3(4, 1, NG), 256>>>(Cin, outAq, LQQ, LCC);
}

// round 7
// speedup vs baseline: 1.7685x; 1.0435x over previous
#include <cuda_runtime.h>
#include <cuda_bf16.h>
#include <stdint.h>
#include <math.h>

// Problem constants: B=16, X=4, I=8 -> G=512 groups; Lc=256, Lq=128, H=512
#define NG 512
#define LCC 256
#define LQQ 128
#define HD 512
#define FSCALE 100.0f
#define FPEN 1.0e12f   // NEG_BIG * SCALE

// Scratch (static device globals: allocation-free per harness rules)
__device__ float g_Pc[NG * LCC * LQQ];   // row-softmax probs * mask  [c][q]
__device__ float g_Pq[NG * LCC * LQQ];   // col-softmax probs * mask  [c][q]
__device__ float g_invC[NG * LCC];
__device__ float g_invQ[NG * LQQ];

// ---------------------------------------------------------------------------
// helpers
// ---------------------------------------------------------------------------
static __device__ __forceinline__ uint32_t smem_u32(const void* p) {
    uint32_t a;
    asm("{ .reg .u64 t; cvta.to.shared.u64 t, %1; cvt.u32.u64 %0, t; }"
        : "=r"(a) : "l"(p));
    return a;
}

// pack two floats as bf16x2 {lo, hi}
static __device__ __forceinline__ uint32_t pack_bf2(float lo, float hi) {
    uint32_t r;
    asm("cvt.rn.bf16x2.f32 %0, %1, %2;" : "=r"(r) : "f"(hi), "f"(lo));
    return r;
}

// split a float4 into bf16 hi/lo pairs and store 8B each to smem
static __device__ __forceinline__ void split_store(uint8_t* sh, uint8_t* sl,
                                                   int off, float4 v) {
    float hx = __bfloat162float(__float2bfloat16(v.x));
    float hy = __bfloat162float(__float2bfloat16(v.y));
    float hz = __bfloat162float(__float2bfloat16(v.z));
    float hw = __bfloat162float(__float2bfloat16(v.w));
    uint2 H, L;
    H.x = pack_bf2(hx, hy);
    H.y = pack_bf2(hz, hw);
    L.x = pack_bf2(v.x - hx, v.y - hy);
    L.y = pack_bf2(v.z - hz, v.w - hw);
    *(uint2*)(sh + off) = H;
    *(uint2*)(sl + off) = L;
}

static __device__ __forceinline__ void ldm4(uint32_t* r, uint32_t a) {
    asm volatile("ldmatrix.sync.aligned.m8n8.x4.shared.b16 {%0,%1,%2,%3}, [%4];"
                 : "=r"(r[0]), "=r"(r[1]), "=r"(r[2]), "=r"(r[3]) : "r"(a));
}
static __device__ __forceinline__ void ldm4t(uint32_t* r, uint32_t a) {
    asm volatile("ldmatrix.sync.aligned.m8n8.x4.trans.shared.b16 {%0,%1,%2,%3}, [%4];"
                 : "=r"(r[0]), "=r"(r[1]), "=r"(r[2]), "=r"(r[3]) : "r"(a));
}

static __device__ __forceinline__ void mma16816(float* d, const uint32_t* a,
                                                const uint32_t* b) {
    asm volatile(
        "mma.sync.aligned.m16n8k16.row.col.f32.bf16.bf16.f32 "
        "{%0,%1,%2,%3}, {%4,%5,%6,%7}, {%8,%9}, {%0,%1,%2,%3};"
        : "+f"(d[0]), "+f"(d[1]), "+f"(d[2]), "+f"(d[3])
        : "r"(a[0]), "r"(a[1]), "r"(a[2]), "r"(a[3]), "r"(b[0]), "r"(b[1]));
}

// ---------------------------------------------------------------------------
// Row L2 inverse norms. One warp per row of H=512 floats.
// ---------------------------------------------------------------------------
__global__ void norm_kernel(const float* __restrict__ X, int nrows, int sel) {
    int gw   = (blockIdx.x * blockDim.x + threadIdx.x) >> 5;
    int lane = threadIdx.x & 31;
    if (gw >= nrows) return;
    const float4* row = (const float4*)(X + (size_t)gw * HD);
    float s = 0.f;
#pragma unroll
    for (int i = 0; i < HD / 128; i++) {
        float4 v = row[lane + 32 * i];
        s = fmaf(v.x, v.x, fmaf(v.y, v.y, fmaf(v.z, v.z, fmaf(v.w, v.w, s))));
    }
#pragma unroll
    for (int o = 16; o; o >>= 1) s += __shfl_xor_sync(0xffffffffu, s, o);
    if (lane == 0) {
        float inv = 1.f / fmaxf(sqrtf(s), 1e-12f);
        if (sel) g_invQ[gw] = inv; else g_invC[gw] = inv;
    }
}

// ---------------------------------------------------------------------------
// Fused: S = masked scaled cosine logits (HMMA bf16 hi/lo) for the WHOLE group
// (256x128) kept in smem, then row softmax -> g_Pc, col softmax -> g_Pq,
// plus both mask outputs. One CTA per group, 512 threads (16 warps, 4m x 4n).
// Register-prefetch double buffering on the K loop.
// ---------------------------------------------------------------------------
#define OFF_S      0
#define SSTRIDE    132                       // floats; keeps float4 alignment
#define OFF_AH     (256 * SSTRIDE * 4)       // 135168
#define OFF_AL     (OFF_AH + 20480)
#define OFF_BH     (OFF_AL + 20480)
#define OFF_BL     (OFF_BH + 10240)
#define OFF_IC     (OFF_BL + 10240)          // 256 f
#define OFF_CM     (OFF_IC + 1024)           // 256 f
#define OFF_IQ     (OFF_CM + 1024)           // 128 f
#define OFF_QM     (OFF_IQ + 512)            // 128 f
#define OFF_RMAX   (OFF_QM + 512)            // 256 f
#define OFF_RINV   (OFF_RMAX + 1024)         // 256 f
#define OFF_CMAX   (OFF_RINV + 1024)         // 128 f
#define OFF_CINV   (OFF_CMAX + 512)          // 128 f
#define OFF_PM     (OFF_CINV + 512)          // 4*128 f
#define OFF_PS     (OFF_PM + 2048)           // 4*128 f
#define SMEM_FUSED (OFF_PS + 2048)           // 206848 bytes

__global__ __launch_bounds__(512, 1) void fused_S(
    const float* __restrict__ Cin, const float* __restrict__ Qin,
    const float* __restrict__ cm, const float* __restrict__ qm,
    float* __restrict__ outM, float* __restrict__ outMT) {
    extern __shared__ __align__(16) uint8_t dsm[];
    float* S      = (float*)(dsm + OFF_S);
    uint8_t* Ah   = dsm + OFF_AH;
    uint8_t* Al   = dsm + OFF_AL;
    uint8_t* Bh   = dsm + OFF_BH;
    uint8_t* Bl   = dsm + OFF_BL;
    float* s_ic   = (float*)(dsm + OFF_IC);
    float* s_cm   = (float*)(dsm + OFF_CM);
    float* s_iq   = (float*)(dsm + OFF_IQ);
    float* s_qm   = (float*)(dsm + OFF_QM);
    float* rowmax = (float*)(dsm + OFF_RMAX);
    float* rowinv = (float*)(dsm + OFF_RINV);
    float* colmax = (float*)(dsm + OFF_CMAX);
    float* colinv = (float*)(dsm + OFF_CINV);
    float* pm     = (float*)(dsm + OFF_PM);
    float* ps     = (float*)(dsm + OFF_PS);

    int t = threadIdx.x, lane = t & 31, wid = t >> 5;
    int wm = wid & 3, wn = wid >> 2;
    int g = blockIdx.x;
    if (t < 256) { s_ic[t] = g_invC[g * LCC + t] * FSCALE; s_cm[t] = cm[g * LCC + t]; }
    else if (t < 384) { int q = t - 256; s_iq[q] = g_invQ[g * LQQ + q]; s_qm[q] = qm[g * LQQ + q]; }
    const float* Ag = Cin + (size_t)g * LCC * HD;
    const float* Bg = Qin + (size_t)g * LQQ * HD;

    int rA = (t + 0) >> 3, cA = t & 7;       // per-thread A/B tile coords
    float4 pvA[4], pvB[2];
#pragma unroll
    for (int i = 0; i < 4; i++) {
        int idx = t + i * 512;
        pvA[i] = *(const float4*)(Ag + (size_t)(idx >> 3) * HD + (idx & 7) * 4);
    }
#pragma unroll
    for (int i = 0; i < 2; i++) {
        int idx = t + i * 512;
        pvB[i] = *(const float4*)(Bg + (size_t)(idx >> 3) * HD + (idx & 7) * 4);
    }
    __syncthreads();

    // ---- mask outputs (independent of GEMM; fills LDG latency) ----
    {
        float* oM = outM + (size_t)g * LCC * LQQ;
#pragma unroll
        for (int i = 0; i < 16; i++) {
            int base = (i * 512 + t) * 4;
            int r = base >> 7, c = base & 127;
            float cv = s_cm[r];
            float4 o = {cv * s_qm[c], cv * s_qm[c + 1], cv * s_qm[c + 2], cv * s_qm[c + 3]};
            *(float4*)(oM + base) = o;
        }
        float* oT = outMT + (size_t)g * LCC * LQQ;
#pragma unroll
        for (int i = 0; i < 16; i++) {
            int base = (i * 512 + t) * 4;
            int r = base >> 8, c = base & 255;
            float qv = s_qm[r];
            float4 o = {qv * s_cm[c], qv * s_cm[c + 1], qv * s_cm[c + 2], qv * s_cm[c + 3]};
            *(float4*)(oT + base) = o;
        }
    }

    // ---- K loop: 16 chunks of BK=32, register-prefetch pipelined ----
    float acc[4][4][4] = {};
    for (int kc = 0; kc < 16; kc++) {
#pragma unroll
        for (int i = 0; i < 4; i++) {
            int idx = t + i * 512;
            split_store(Ah, Al, (idx >> 3) * 80 + (idx & 7) * 8, pvA[i]);
        }
#pragma unroll
        for (int i = 0; i < 2; i++) {
            int idx = t + i * 512;
            split_store(Bh, Bl, (idx >> 3) * 80 + (idx & 7) * 8, pvB[i]);
        }
        __syncthreads();
        if (kc < 15) {
            int k0 = (kc + 1) * 32;
#pragma unroll
            for (int i = 0; i < 4; i++) {
                int idx = t + i * 512;
                pvA[i] = *(const float4*)(Ag + (size_t)(idx >> 3) * HD + k0 + (idx & 7) * 4);
            }
#pragma unroll
            for (int i = 0; i < 2; i++) {
                int idx = t + i * 512;
                pvB[i] = *(const float4*)(Bg + (size_t)(idx >> 3) * HD + k0 + (idx & 7) * 4);
            }
        }
#pragma unroll
        for (int k16 = 0; k16 < 2; k16++) {
            uint32_t af[4][4], bh[4][2], bl[4][2];
            int colb = k16 * 32 + ((lane >> 4) & 1) * 16;
            int ra = wm * 64 + (lane & 15);
            int rb = wn * 32 + (lane & 15);
#pragma unroll
            for (int bg2 = 0; bg2 < 2; bg2++) {
                uint32_t r4[4];
                ldm4(r4, smem_u32(Bh + (rb + bg2 * 16) * 80 + colb));
                bh[bg2 * 2][0] = r4[0]; bh[bg2 * 2][1] = r4[2];
                bh[bg2 * 2 + 1][0] = r4[1]; bh[bg2 * 2 + 1][1] = r4[3];
                ldm4(r4, smem_u32(Bl + (rb + bg2 * 16) * 80 + colb));
                bl[bg2 * 2][0] = r4[0]; bl[bg2 * 2][1] = r4[2];
                bl[bg2 * 2 + 1][0] = r4[1]; bl[bg2 * 2 + 1][1] = r4[3];
            }
#pragma unroll
            for (int fm = 0; fm < 4; fm++)
                ldm4(af[fm], smem_u32(Ah + (ra + fm * 16) * 80 + colb));
#pragma unroll
            for (int fm = 0; fm < 4; fm++)
#pragma unroll
                for (int ni = 0; ni < 4; ni++) {
                    mma16816(acc[fm][ni], af[fm], bh[ni]);
                    mma16816(acc[fm][ni], af[fm], bl[ni]);
                }
#pragma unroll
            for (int fm = 0; fm < 4; fm++)
                ldm4(af[fm], smem_u32(Al + (ra + fm * 16) * 80 + colb));
#pragma unroll
            for (int fm = 0; fm < 4; fm++)
#pragma unroll
                for (int ni = 0; ni < 4; ni++)
                    mma16816(acc[fm][ni], af[fm], bh[ni]);
        }
        __syncthreads();
    }
    (void)rA; (void)cA;

    // ---- logits -> S smem ----
    int g2 = lane >> 2, t4 = lane & 3;
#pragma unroll
    for (int fm = 0; fm < 4; fm++)
#pragma unroll
        for (int half = 0; half < 2; half++) {
            int row = wm * 64 + fm * 16 + g2 + half * 8;
            float ic = s_ic[row], cv = s_cm[row];
#pragma unroll
            for (int ni = 0; ni < 4; ni++) {
                int col = wn * 32 + ni * 8 + t4 * 2;
                S[row * SSTRIDE + col]     = acc[fm][ni][half * 2]     * ic * s_iq[col]     - FPEN * (1.f - cv * s_qm[col]);
                S[row * SSTRIDE + col + 1] = acc[fm][ni][half * 2 + 1] * ic * s_iq[col + 1] - FPEN * (1.f - cv * s_qm[col + 1]);
            }
        }
    __syncthreads();

    // ---- row softmax stats (rotate col by lane to avoid bank conflicts) ----
    if (t < 256) {
        const float* sr = S + t * SSTRIDE;
        float m = -3.0e38f;
#pragma unroll 8
        for (int cc = 0; cc < 128; cc++) m = fmaxf(m, sr[(cc + lane) & 127]);
        float s = 0.f;
#pragma unroll 8
        for (int cc = 0; cc < 128; cc++) s += __expf(sr[(cc + lane) & 127] - m);
        rowmax[t] = m;
        rowinv[t] = s_cm[t] / s;
    }
    // ---- col partial stats ----
    {
        int c = t & 127, part = t >> 7;
        const float* sc = S + (part * 64) * SSTRIDE + c;
        float m = -3.0e38f;
#pragma unroll 8
        for (int r2 = 0; r2 < 64; r2++) m = fmaxf(m, sc[r2 * SSTRIDE]);
        float s = 0.f;
#pragma unroll 8
        for (int r2 = 0; r2 < 64; r2++) s += __expf(sc[r2 * SSTRIDE] - m);
        pm[part * 128 + c] = m;
        ps[part * 128 + c] = s;
    }
    __syncthreads();
    if (t < 128) {
        float M = fmaxf(fmaxf(pm[t], pm[128 + t]), fmaxf(pm[256 + t], pm[384 + t]));
        float T = ps[t] * __expf(pm[t] - M) + ps[128 + t] * __expf(pm[128 + t] - M)
                + ps[256 + t] * __expf(pm[256 + t] - M) + ps[384 + t] * __expf(pm[384 + t] - M);
        colmax[t] = M;
        colinv[t] = s_qm[t] / T;
    }
    __syncthreads();

    // ---- write P_c and P_q ----
    float* Pc = g_Pc + (size_t)g * LCC * LQQ;
    float* Pq = g_Pq + (size_t)g * LCC * LQQ;
#pragma unroll
    for (int i = 0; i < 16; i++) {
        int base = (i * 512 + t) * 4;
        int r = base >> 7, c = base & 127;
        float4 v = *(const float4*)(S + r * SSTRIDE + c);
        float rm = rowmax[r], ri = rowinv[r], cv = s_cm[r];
        float4 pc, pq;
        pc.x = __expf(v.x - rm) * ri * s_qm[c];
        pc.y = __expf(v.y - rm) * ri * s_qm[c + 1];
        pc.z = __expf(v.z - rm) * ri * s_qm[c + 2];
        pc.w = __expf(v.w - rm) * ri * s_qm[c + 3];
        pq.x = __expf(v.x - colmax[c])     * colinv[c]     * cv;
        pq.y = __expf(v.y - colmax[c + 1]) * colinv[c + 1] * cv;
        pq.z = __expf(v.z - colmax[c + 2]) * colinv[c + 2] * cv;
        pq.w = __expf(v.w - colmax[c + 3]) * colinv[c + 3] * cv;
        *(float4*)(Pc + base) = pc;
        *(float4*)(Pq + base) = pq;
    }
}

// ---------------------------------------------------------------------------
// NN GEMM via HMMA bf16 hi/lo: out[M,512] = A[M,K] @ B[K,512] per group.
// ATRANS=false: A = g_Pc (row-major [m][k]);  Ac: M=256, K=128.
// ATRANS=true : A = g_Pq (stored [k=c][m=q]); Aq: M=128, K=256 (A^T product).
// B (Q or C) is [K][512] row-major -> ldmatrix.trans.
// Register-prefetch double buffering on the K loop.
// ---------------------------------------------------------------------------
template<bool ATRANS>
__global__ __launch_bounds__(256) void nn_gemm(const float* __restrict__ Bg0,
                                               float* __restrict__ out,
                                               int M, int K) {
    constexpr int ASZ = ATRANS ? 8704 : 10240;
    __shared__ __align__(16) uint8_t sm[2 * ASZ + 2 * 8704];
    uint8_t* Ah = sm;
    uint8_t* Al = sm + ASZ;
    uint8_t* Bh = sm + 2 * ASZ;
    uint8_t* Bl = sm + 2 * ASZ + 8704;
    int t = threadIdx.x, lane = t & 31, wid = t >> 5;
    int wm = wid & 1, wn = wid >> 1;
    int g = blockIdx.z, m0 = blockIdx.y * 128, n0 = blockIdx.x * 128;
    const float* Ag = (ATRANS ? g_Pq : g_Pc) + (size_t)g * LCC * LQQ;
    const float* Bg = Bg0 + (size_t)g * K * HD;
    float acc[4][4][4] = {};
    int KCH = K >> 5;

    float4 pvA[4], pvB[4];
#pragma unroll
    for (int i = 0; i < 4; i++) {
        int idx = t + i * 256;
        if (!ATRANS)
            pvA[i] = *(const float4*)(Ag + (size_t)(m0 + (idx >> 3)) * K + (idx & 7) * 4);
        else
            pvA[i] = *(const float4*)(Ag + (size_t)(idx >> 5) * M + (idx & 31) * 4);
        pvB[i] = *(const float4*)(Bg + (size_t)(idx >> 5) * HD + n0 + (idx & 31) * 4);
    }

    for (int kc = 0; kc < KCH; kc++) {
#pragma unroll
        for (int i = 0; i < 4; i++) {
            int idx = t + i * 256;
            if (!ATRANS)
                split_store(Ah, Al, (idx >> 3) * 80 + (idx & 7) * 8, pvA[i]);
            else
                split_store(Ah, Al, (idx >> 5) * 272 + (idx & 31) * 8, pvA[i]);
            split_store(Bh, Bl, (idx >> 5) * 272 + (idx & 31) * 8, pvB[i]);
        }
        __syncthreads();
        if (kc + 1 < KCH) {
            int k0 = (kc + 1) * 32;
#pragma unroll
            for (int i = 0; i < 4; i++) {
                int idx = t + i * 256;
                if (!ATRANS)
                    pvA[i] = *(const float4*)(Ag + (size_t)(m0 + (idx >> 3)) * K + k0 + (idx & 7) * 4);
                else
                    pvA[i] = *(const float4*)(Ag + (size_t)(k0 + (idx >> 5)) * M + (idx & 31) * 4);
                pvB[i] = *(const float4*)(Bg + (size_t)(k0 + (idx >> 5)) * HD + n0 + (idx & 31) * 4);
            }
        }
#pragma unroll
        for (int k16 = 0; k16 < 2; k16++) {
            uint32_t ah[4][4], al[4][4], bh[4][2], bl[4][2];
            if (!ATRANS) {
                int colb = k16 * 32 + ((lane >> 4) & 1) * 16;
                int ra = wm * 64 + (lane & 15);
#pragma unroll
                for (int fm = 0; fm < 4; fm++) {
                    ldm4(ah[fm], smem_u32(Ah + (ra + fm * 16) * 80 + colb));
                    ldm4(al[fm], smem_u32(Al + (ra + fm * 16) * 80 + colb));
                }
            } else {
                int row = k16 * 16 + (lane & 7) + ((lane >> 4) & 1) * 8;
                int cb  = wm * 128 + ((lane >> 3) & 1) * 16;
#pragma unroll
                for (int fm = 0; fm < 4; fm++) {
                    ldm4t(ah[fm], smem_u32(Ah + row * 272 + cb + fm * 32));
                    ldm4t(al[fm], smem_u32(Al + row * 272 + cb + fm * 32));
                }
            }
            {
                int rowb = k16 * 16 + (lane & 7) + ((lane >> 3) & 1) * 8;
                int cbb  = wn * 64 + ((lane >> 4) & 1) * 16;
#pragma unroll
                for (int bg = 0; bg < 2; bg++) {
                    uint32_t r4[4];
                    ldm4t(r4, smem_u32(Bh + rowb * 272 + cbb + bg * 32));
                    bh[bg * 2][0] = r4[0]; bh[bg * 2][1] = r4[1];
                    bh[bg * 2 + 1][0] = r4[2]; bh[bg * 2 + 1][1] = r4[3];
                    ldm4t(r4, smem_u32(Bl + rowb * 272 + cbb + bg * 32));
                    bl[bg * 2][0] = r4[0]; bl[bg * 2][1] = r4[1];
                    bl[bg * 2 + 1][0] = r4[2]; bl[bg * 2 + 1][1] = r4[3];
                }
            }
#pragma unroll
            for (int fm = 0; fm < 4; fm++)
#pragma unroll
                for (int ni = 0; ni < 4; ni++) {
                    mma16816(acc[fm][ni], ah[fm], bh[ni]);
                    mma16816(acc[fm][ni], ah[fm], bl[ni]);
                    mma16816(acc[fm][ni], al[fm], bh[ni]);
                }
        }
        __syncthreads();
    }
    int g2 = lane >> 2, t4 = lane & 3;
#pragma unroll
    for (int fm = 0; fm < 4; fm++)
#pragma unroll
        for (int half = 0; half < 2; half++) {
            int row = m0 + wm * 64 + fm * 16 + g2 + half * 8;
            float* dst = out + ((size_t)g * M + row) * HD + n0;
#pragma unroll
            for (int ni = 0; ni < 4; ni++) {
                int col = wn * 32 + ni * 8 + t4 * 2;
                float2 o = {acc[fm][ni][half * 2], acc[fm][ni][half * 2 + 1]};
                *(float2*)(dst + col) = o;
            }
        }
}

// ---------------------------------------------------------------------------
extern "C" void kernel_launch(void* const* d_in, const int* in_sizes, int n_in,
                              void* d_out, int out_size) {
    const float* Cin = (const float*)d_in[0];
    const float* Qin = (const float*)d_in[1];
    const float* cm  = (const float*)d_in[2];
    const float* qm  = (const float*)d_in[3];
    float* out   = (float*)d_out;
    float* outAc = out;
    float* outAq = outAc + (size_t)NG * LCC * HD;
    float* outM  = outAq + (size_t)NG * LQQ * HD;
    float* outMT = outM  + (size_t)NG * LCC * LQQ;

    cudaFuncSetAttribute(fused_S, cudaFuncAttributeMaxDynamicSharedMemorySize,
                         SMEM_FUSED);

    norm_kernel<<<NG * LCC / 8, 256>>>(Cin, NG * LCC, 0);
    norm_kernel<<<NG * LQQ / 8, 256>>>(Qin, NG * LQQ, 1);
    fused_S<<<NG, 512, SMEM_FUSED>>>(Cin, Qin, cm, qm, outM, outMT);
    nn_gemm<false><<<dim3(4, 2, NG), 256>>>(Qin, outAc, LCC, LQQ);
    nn_gemm<true ><<<dim3(4, 1, NG), 256>>>(Cin, outAq, LQQ, LCC);
}